// round 13
// baseline (speedup 1.0000x reference)
#include <cuda_runtime.h>
#include <cuda_fp16.h>
#include <cstdint>

#define D65 65
#define K0  4225
#define KP  4352            // padded K (single-term fp16)
#define MROWS 8192
#define LSEQ 1024
#define BK  64
#define NT  (KP / BK)       // 68 k-tiles of 64

// ---------------- scratch ----------------
__device__ __half g_A[(size_t)MROWS * KP];  // [m][Xh]
__device__ __half g_R[(size_t)MROWS * KP];  // [m][Rh]
__device__ __half g_B[(size_t)KP    * KP];  // [(b,d)][Wh] (pads stay 0)
__device__ __half g_Q[(size_t)MROWS * KP];  // [m][Qh]

// smem: 2 stages x (A 64x64 + B 128x64 fp16), 128B rows, XOR swizzle
// stage layout: rows 0..63 = A, rows 64..191 = B
#define STAGE_B   (192 * 128)            // 24576 B
#define SMEM_SZ   (2 * STAGE_B)          // 49152 B

// ---------------- PTX helpers ----------------
__device__ __forceinline__ uint32_t s2u(const void* p) {
    uint32_t a;
    asm("{ .reg .u64 t; cvta.to.shared.u64 t, %1; cvt.u32.u64 %0, t; }"
        : "=r"(a) : "l"(p));
    return a;
}
__device__ __forceinline__ void cp16(uint32_t s, const void* g) {
    asm volatile("cp.async.cg.shared.global [%0], [%1], 16;\n" :: "r"(s), "l"(g));
}
#define CP_COMMIT() asm volatile("cp.async.commit_group;\n" ::: "memory")
#define CP_WAIT1()  asm volatile("cp.async.wait_group 1;\n" ::: "memory")

#define LDM_X4(r0, r1, r2, r3, a)                                              \
    asm volatile("ldmatrix.sync.aligned.m8n8.x4.shared.b16 {%0,%1,%2,%3}, [%4];" \
        : "=r"(r0), "=r"(r1), "=r"(r2), "=r"(r3) : "r"(a))

#define MMA16816(c, a, b0, b1)                                                 \
    asm volatile("mma.sync.aligned.m16n8k16.row.col.f32.f16.f16.f32 "          \
        "{%0,%1,%2,%3}, {%4,%5,%6,%7}, {%8,%9}, {%0,%1,%2,%3};"                \
        : "+f"((c)[0]), "+f"((c)[1]), "+f"((c)[2]), "+f"((c)[3])               \
        : "r"((a)[0]), "r"((a)[1]), "r"((a)[2]), "r"((a)[3]),                  \
          "r"(b0), "r"(b1))

// ---------------- prep kernels ----------------
__global__ void prep_XR(const float* __restrict__ l1, const float* __restrict__ l2,
                        const float* __restrict__ h1, const float* __restrict__ h2) {
    int m = blockIdx.y;
    int k = blockIdx.x * blockDim.x + threadIdx.x;   // 0..KP-1
    float xv = 0.f, rv = 0.f;
    if (k < K0) {
        int a = k / D65, c = k - a * D65;
        float l1v = (a < 64) ? l1[m * 64 + a] : 1.0f;
        float l2v = (a < 64) ? l2[m * 64 + a] : 1.0f;
        xv = l1v * h1[m * D65 + c];
        rv = l2v * h2[m * D65 + c];
    }
    size_t base = (size_t)m * KP;
    g_A[base + k] = __float2half_rn(xv);
    g_R[base + k] = __float2half_rn(rv);
}

// g_B[(b*65+d)][a*65+c] = W[a][b][c][d] rounded to fp16
__global__ void prep_W(const float* __restrict__ W) {
    __shared__ float s[K0];
    int ab = blockIdx.x;
    int a = ab / D65, b = ab - a * D65;
    const float* Wab = W + (size_t)ab * K0;
    for (int i = threadIdx.x; i < K0; i += blockDim.x) s[i] = Wab[i];
    __syncthreads();
    for (int i = threadIdx.x; i < K0; i += blockDim.x) {
        int d = i / D65, c = i - d * D65;
        g_B[(size_t)(b * D65 + d) * KP + a * D65 + c] = __float2half_rn(s[c * D65 + d]);
    }
}

// ---------------- stage loader: A 64x64 + B 128x64 fp16 -------------------
// smem addr: row*128 + ((chunk ^ (row&7)) * 16); A rows 0..63, B rows 64..191
__device__ __forceinline__ void load_stage(uint32_t smS,
                                           const __half* Ab,
                                           const __half* Bb, int tid) {
#pragma unroll
    for (int t = 0; t < 12; t++) {
        int id = tid + t * 128;
        int r = id >> 3, c = id & 7;
        uint32_t off = r * 128 + ((c ^ (r & 7)) << 4);
        const __half* src = (r < 64) ? (Ab + (size_t)r * KP + c * 8)
                                     : (Bb + (size_t)(r - 64) * KP + c * 8);
        cp16(smS + off, src);
    }
}

// ---------------- HMMA mainloop: acc[2][8][4] = A(64xKP) * B(128xKP)^T ----
// 4 warps: warp_m = wid&1 (2 x 32 rows), warp_n = wid>>1 (2 x 64 cols)
__device__ __forceinline__ void hmma_loop(const __half* Abase,
                                          const __half* Bbase,
                                          uint32_t smb, int tid,
                                          float acc[2][8][4]) {
    int lane = tid & 31, wid = tid >> 5;
    int warp_m = wid & 1, warp_n = wid >> 1;

#pragma unroll
    for (int i = 0; i < 2; i++)
#pragma unroll
        for (int j = 0; j < 8; j++)
#pragma unroll
            for (int t = 0; t < 4; t++) acc[i][j][t] = 0.f;

    int a_row  = 32 * warp_m + (lane & 7) + ((lane >> 3) & 1) * 8;
    int a_ch   = (lane >> 4) & 1;
    int b_row  = 64 + 64 * warp_n + (lane & 7) + ((lane >> 4) & 1) * 8;
    int b_ch   = (lane >> 3) & 1;

    load_stage(smb, Abase, Bbase, tid);      // k-tile 0 -> buf0
    CP_COMMIT();

    for (int kt = 0; kt < NT; kt++) {
        __syncthreads();                     // buf (kt+1)%2 free (kt-1 compute done)
        if (kt + 1 < NT) {
            load_stage(smb + ((kt + 1) & 1) * STAGE_B,
                       Abase + (size_t)(kt + 1) * BK,
                       Bbase + (size_t)(kt + 1) * BK, tid);
        }
        CP_COMMIT();
        CP_WAIT1();                          // group kt landed (kt+1 may fly)
        __syncthreads();                     // cross-thread visibility of buf kt
        uint32_t sS = smb + (kt & 1) * STAGE_B;

#pragma unroll
        for (int ks = 0; ks < 4; ks++) {
            int kc = ks * 2;                 // base 16B-chunk of this k16
            uint32_t af[2][4];
#pragma unroll
            for (int i = 0; i < 2; i++) {
                int r = a_row + 16 * i;
                uint32_t addr = sS + r * 128 + (((kc + a_ch) ^ (r & 7)) << 4);
                LDM_X4(af[i][0], af[i][1], af[i][2], af[i][3], addr);
            }
            uint32_t bf[8][2];
#pragma unroll
            for (int j2 = 0; j2 < 4; j2++) {
                int r = b_row + 16 * j2;
                uint32_t addr = sS + r * 128 + (((kc + b_ch) ^ (r & 7)) << 4);
                LDM_X4(bf[2 * j2][0], bf[2 * j2][1],
                       bf[2 * j2 + 1][0], bf[2 * j2 + 1][1], addr);
            }
#pragma unroll
            for (int i = 0; i < 2; i++)
#pragma unroll
                for (int j = 0; j < 8; j++)
                    MMA16816(acc[i][j], af[i], bf[j][0], bf[j][1]);
        }
    }
}

// ---------------- GEMM1: Q = X @ W^T, epilogue fp16 -----------------------
__global__ void __launch_bounds__(128, 4) gemm1_kernel() {
    extern __shared__ char sm[];
    uint32_t smb = s2u(sm);
    int tid = threadIdx.x, lane = tid & 31, wid = tid >> 5;
    int warp_m = wid & 1, warp_n = wid >> 1;
    int brow = blockIdx.y * 64, bn = blockIdx.x * 128;

    float acc[2][8][4];
    hmma_loop(g_A + (size_t)brow * KP, g_B + (size_t)bn * KP, smb, tid, acc);

    int row0 = brow + 32 * warp_m + (lane >> 2);
    int col0 = bn + 64 * warp_n + (lane & 3) * 2;
#pragma unroll
    for (int i = 0; i < 2; i++) {
#pragma unroll
        for (int j = 0; j < 8; j++) {
#pragma unroll
            for (int half = 0; half < 2; half++) {
                int r = row0 + 16 * i + 8 * half;
                int c = col0 + 8 * j;
                __half2 hh;
                hh.x = __float2half_rn(acc[i][j][2 * half]);
                hh.y = __float2half_rn(acc[i][j][2 * half + 1]);
                *reinterpret_cast<__half2*>(&g_Q[(size_t)r * KP + c]) = hh;
            }
        }
    }
}

// ---------------- GEMM2: out[n] = Q[n] @ R[n]^T, fp32 epilogue ------------
__global__ void __launch_bounds__(128, 4) gemm2_kernel(float* __restrict__ out) {
    extern __shared__ char sm[];
    uint32_t smb = s2u(sm);
    int tid = threadIdx.x, lane = tid & 31, wid = tid >> 5;
    int warp_m = wid & 1, warp_n = wid >> 1;
    int nb = blockIdx.z;
    int brow = blockIdx.y * 64, bn = blockIdx.x * 128;

    float acc[2][8][4];
    hmma_loop(g_Q + ((size_t)nb * LSEQ + brow) * KP,
              g_R + ((size_t)nb * LSEQ + bn) * KP, smb, tid, acc);

    int row0 = brow + 32 * warp_m + (lane >> 2);
    int col0 = bn + 64 * warp_n + (lane & 3) * 2;
    float* obase = out + (size_t)nb * LSEQ * LSEQ;
#pragma unroll
    for (int i = 0; i < 2; i++) {
#pragma unroll
        for (int j = 0; j < 8; j++) {
#pragma unroll
            for (int half = 0; half < 2; half++) {
                int r = row0 + 16 * i + 8 * half;
                int c = col0 + 8 * j;
                float2 v = make_float2(acc[i][j][2 * half], acc[i][j][2 * half + 1]);
                *reinterpret_cast<float2*>(&obase[(size_t)r * LSEQ + c]) = v;
            }
        }
    }
}

// ---------------- launcher ------------------------------------------------
extern "C" void kernel_launch(void* const* d_in, const int* in_sizes, int n_in,
                              void* d_out, int out_size) {
    const float* l1 = (const float*)d_in[0];
    const float* l2 = (const float*)d_in[1];
    const float* h1 = (const float*)d_in[3];
    const float* h2 = (const float*)d_in[4];
    const float* W  = (const float*)d_in[6];
    float* out = (float*)d_out;

    cudaFuncSetAttribute(gemm1_kernel, cudaFuncAttributeMaxDynamicSharedMemorySize, SMEM_SZ);
    cudaFuncSetAttribute(gemm2_kernel, cudaFuncAttributeMaxDynamicSharedMemorySize, SMEM_SZ);

    prep_XR<<<dim3(17, MROWS), 256>>>(l1, l2, h1, h2);
    prep_W<<<D65 * D65, 256>>>(W);
    gemm1_kernel<<<dim3(34, 128), 128, SMEM_SZ>>>();
    gemm2_kernel<<<dim3(8, 16, 8), 128, SMEM_SZ>>>(out);
}

// round 15
// speedup vs baseline: 1.4651x; 1.4651x over previous
#include <cuda_runtime.h>
#include <cuda_fp16.h>
#include <cstdint>

#define D65 65
#define K0  4225
#define KP  4352            // array stride / N padding (34 x 128)
#define MROWS 8192
#define LSEQ 1024
#define BK  64
#define NT  67              // ceil(4225/64): k-tile 67 is all zero padding -> skipped

// ---------------- scratch ----------------
__device__ __half g_A[(size_t)MROWS * KP];  // [m][Xh]
__device__ __half g_R[(size_t)MROWS * KP];  // [m][Rh]
__device__ __half g_B[(size_t)KP    * KP];  // [(b,d)][Wh] (pads stay 0)
__device__ __half g_Q[(size_t)MROWS * KP];  // [m][Qh]

// smem: 3 stages x (A 128x64 + B 128x64 fp16), 128B rows, XOR swizzle
#define TILE_B    (128 * 128)            // 16384 B per tile
#define STAGE_B   (2 * TILE_B)           // 32768 B
#define SMEM_SZ   (3 * STAGE_B)          // 98304 B

// ---------------- PTX helpers ----------------
__device__ __forceinline__ uint32_t s2u(const void* p) {
    uint32_t a;
    asm("{ .reg .u64 t; cvta.to.shared.u64 t, %1; cvt.u32.u64 %0, t; }"
        : "=r"(a) : "l"(p));
    return a;
}
__device__ __forceinline__ void cp16(uint32_t s, const void* g) {
    asm volatile("cp.async.cg.shared.global [%0], [%1], 16;\n" :: "r"(s), "l"(g));
}
#define CP_COMMIT() asm volatile("cp.async.commit_group;\n" ::: "memory")
#define CP_WAIT1()  asm volatile("cp.async.wait_group 1;\n" ::: "memory")

#define LDM_X4(r0, r1, r2, r3, a)                                              \
    asm volatile("ldmatrix.sync.aligned.m8n8.x4.shared.b16 {%0,%1,%2,%3}, [%4];" \
        : "=r"(r0), "=r"(r1), "=r"(r2), "=r"(r3) : "r"(a))

#define MMA16816(c, a, b0, b1)                                                 \
    asm volatile("mma.sync.aligned.m16n8k16.row.col.f32.f16.f16.f32 "          \
        "{%0,%1,%2,%3}, {%4,%5,%6,%7}, {%8,%9}, {%0,%1,%2,%3};"                \
        : "+f"((c)[0]), "+f"((c)[1]), "+f"((c)[2]), "+f"((c)[3])               \
        : "r"((a)[0]), "r"((a)[1]), "r"((a)[2]), "r"((a)[3]),                  \
          "r"(b0), "r"(b1))

// ---------------- prep kernels ----------------
__global__ void prep_XR(const float* __restrict__ l1, const float* __restrict__ l2,
                        const float* __restrict__ h1, const float* __restrict__ h2) {
    int m = blockIdx.y;
    int k = blockIdx.x * blockDim.x + threadIdx.x;   // 0..KP-1
    float xv = 0.f, rv = 0.f;
    if (k < K0) {
        int a = k / D65, c = k - a * D65;
        float l1v = (a < 64) ? l1[m * 64 + a] : 1.0f;
        float l2v = (a < 64) ? l2[m * 64 + a] : 1.0f;
        xv = l1v * h1[m * D65 + c];
        rv = l2v * h2[m * D65 + c];
    }
    size_t base = (size_t)m * KP;
    g_A[base + k] = __float2half_rn(xv);
    g_R[base + k] = __float2half_rn(rv);
}

// g_B[(b*65+d)][a*65+c] = W[a][b][c][d] rounded to fp16
__global__ void prep_W(const float* __restrict__ W) {
    __shared__ float s[K0];
    int ab = blockIdx.x;
    int a = ab / D65, b = ab - a * D65;
    const float* Wab = W + (size_t)ab * K0;
    for (int i = threadIdx.x; i < K0; i += blockDim.x) s[i] = Wab[i];
    __syncthreads();
    for (int i = threadIdx.x; i < K0; i += blockDim.x) {
        int d = i / D65, c = i - d * D65;
        g_B[(size_t)(b * D65 + d) * KP + a * D65 + c] = __float2half_rn(s[c * D65 + d]);
    }
}

// ---------------- stage loader: 128x64 fp16 for A and B -------------------
// smem addr: row*128 + ((chunk ^ (row&7)) * 16), chunk = 16B column index
__device__ __forceinline__ void load_stage(uint32_t smA, uint32_t smB,
                                           const __half* Ab,
                                           const __half* Bb, int tid) {
#pragma unroll
    for (int t = 0; t < 4; t++) {
        int id = tid + t * 256;
        int r = id >> 3, c = id & 7;
        uint32_t off = r * 128 + ((c ^ (r & 7)) << 4);
        cp16(smA + off, Ab + (size_t)r * KP + c * 8);
        cp16(smB + off, Bb + (size_t)r * KP + c * 8);
    }
}

// ---------------- HMMA mainloop: acc[2][8][4] = A(128xK) * B(128xK)^T -----
__device__ __forceinline__ void hmma_loop(const __half* Abase,
                                          const __half* Bbase,
                                          uint32_t smb, int tid,
                                          float acc[2][8][4]) {
    int lane = tid & 31, wid = tid >> 5;
    int warp_m = wid & 3, warp_n = wid >> 2;

#pragma unroll
    for (int i = 0; i < 2; i++)
#pragma unroll
        for (int j = 0; j < 8; j++)
#pragma unroll
            for (int t = 0; t < 4; t++) acc[i][j][t] = 0.f;

    // ldmatrix per-lane rows and 8-element column halves
    int a_row  = 32 * warp_m + (lane & 7) + ((lane >> 3) & 1) * 8;
    int a_ch   = (lane >> 4) & 1;          // 8-elem half -> chunk offset
    int b_row  = 64 * warp_n + (lane & 7) + ((lane >> 4) & 1) * 8;
    int b_ch   = (lane >> 3) & 1;

    load_stage(smb, smb + TILE_B, Abase, Bbase, tid);
    CP_COMMIT();
    load_stage(smb + STAGE_B, smb + STAGE_B + TILE_B, Abase + BK, Bbase + BK, tid);
    CP_COMMIT();

    // rotating stage pointers: s0 = compute stage (kt%3), s2 = load stage ((kt+2)%3)
    uint32_t s0 = smb, s1 = smb + STAGE_B, s2 = smb + 2 * STAGE_B;

    for (int kt = 0; kt < NT; kt++) {
        CP_WAIT1();
        __syncthreads();
        uint32_t sA = s0;
        uint32_t sB = s0 + TILE_B;
        if (kt + 2 < NT) {
            load_stage(s2, s2 + TILE_B,
                       Abase + (size_t)(kt + 2) * BK,
                       Bbase + (size_t)(kt + 2) * BK, tid);
        }
        CP_COMMIT();
        // rotate for next iteration
        uint32_t tmp = s0; s0 = s1; s1 = s2; s2 = tmp;

#pragma unroll
        for (int ks = 0; ks < 4; ks++) {
            int kc = ks * 2;                 // base 16B-chunk of this k16
            uint32_t af[2][4];
#pragma unroll
            for (int i = 0; i < 2; i++) {
                int r = a_row + 16 * i;
                uint32_t addr = sA + r * 128 + (((kc + a_ch) ^ (r & 7)) << 4);
                LDM_X4(af[i][0], af[i][1], af[i][2], af[i][3], addr);
            }
            uint32_t bf[8][2];
#pragma unroll
            for (int j2 = 0; j2 < 4; j2++) {
                int r = b_row + 16 * j2;
                uint32_t addr = sB + r * 128 + (((kc + b_ch) ^ (r & 7)) << 4);
                LDM_X4(bf[2 * j2][0], bf[2 * j2][1],
                       bf[2 * j2 + 1][0], bf[2 * j2 + 1][1], addr);
            }
#pragma unroll
            for (int i = 0; i < 2; i++)
#pragma unroll
                for (int j = 0; j < 8; j++)
                    MMA16816(acc[i][j], af[i], bf[j][0], bf[j][1]);
        }
        // no trailing barrier: next iteration's top barrier protects reuse
    }
}

// ---------------- GEMM1: Q = X @ W^T, epilogue fp16 -----------------------
__global__ void __launch_bounds__(256, 2) gemm1_kernel() {
    extern __shared__ char sm[];
    uint32_t smb = s2u(sm);
    int tid = threadIdx.x, lane = tid & 31, wid = tid >> 5;
    int warp_m = wid & 3, warp_n = wid >> 2;
    int brow = blockIdx.y * 128, bn = blockIdx.x * 128;

    float acc[2][8][4];
    hmma_loop(g_A + (size_t)brow * KP, g_B + (size_t)bn * KP, smb, tid, acc);

    int row0 = brow + 32 * warp_m + (lane >> 2);
    int col0 = bn + 64 * warp_n + (lane & 3) * 2;
#pragma unroll
    for (int i = 0; i < 2; i++) {
#pragma unroll
        for (int j = 0; j < 8; j++) {
#pragma unroll
            for (int half = 0; half < 2; half++) {
                int r = row0 + 16 * i + 8 * half;
                int c = col0 + 8 * j;
                __half2 hh;
                hh.x = __float2half_rn(acc[i][j][2 * half]);
                hh.y = __float2half_rn(acc[i][j][2 * half + 1]);
                *reinterpret_cast<__half2*>(&g_Q[(size_t)r * KP + c]) = hh;
            }
        }
    }
}

// ---------------- GEMM2: out[n] = Q[n] @ R[n]^T, fp32 epilogue ------------
__global__ void __launch_bounds__(256, 2) gemm2_kernel(float* __restrict__ out) {
    extern __shared__ char sm[];
    uint32_t smb = s2u(sm);
    int tid = threadIdx.x, lane = tid & 31, wid = tid >> 5;
    int warp_m = wid & 3, warp_n = wid >> 2;
    int nb = blockIdx.z;
    int brow = blockIdx.y * 128, bn = blockIdx.x * 128;

    float acc[2][8][4];
    hmma_loop(g_Q + ((size_t)nb * LSEQ + brow) * KP,
              g_R + ((size_t)nb * LSEQ + bn) * KP, smb, tid, acc);

    int row0 = brow + 32 * warp_m + (lane >> 2);
    int col0 = bn + 64 * warp_n + (lane & 3) * 2;
    float* obase = out + (size_t)nb * LSEQ * LSEQ;
#pragma unroll
    for (int i = 0; i < 2; i++) {
#pragma unroll
        for (int j = 0; j < 8; j++) {
#pragma unroll
            for (int half = 0; half < 2; half++) {
                int r = row0 + 16 * i + 8 * half;
                int c = col0 + 8 * j;
                float2 v = make_float2(acc[i][j][2 * half], acc[i][j][2 * half + 1]);
                *reinterpret_cast<float2*>(&obase[(size_t)r * LSEQ + c]) = v;
            }
        }
    }
}

// ---------------- launcher ------------------------------------------------
extern "C" void kernel_launch(void* const* d_in, const int* in_sizes, int n_in,
                              void* d_out, int out_size) {
    const float* l1 = (const float*)d_in[0];
    const float* l2 = (const float*)d_in[1];
    const float* h1 = (const float*)d_in[3];
    const float* h2 = (const float*)d_in[4];
    const float* W  = (const float*)d_in[6];
    float* out = (float*)d_out;

    cudaFuncSetAttribute(gemm1_kernel, cudaFuncAttributeMaxDynamicSharedMemorySize, SMEM_SZ);
    cudaFuncSetAttribute(gemm2_kernel, cudaFuncAttributeMaxDynamicSharedMemorySize, SMEM_SZ);

    prep_XR<<<dim3(17, MROWS), 256>>>(l1, l2, h1, h2);
    prep_W<<<D65 * D65, 256>>>(W);
    gemm1_kernel<<<dim3(34, 64), 256, SMEM_SZ>>>();
    gemm2_kernel<<<dim3(8, 8, 8), 256, SMEM_SZ>>>(out);   // grid.x=8: full 1024 cols
}

// round 16
// speedup vs baseline: 1.4673x; 1.0015x over previous
#include <cuda_runtime.h>
#include <cuda_fp16.h>
#include <cstdint>

#define D65 65
#define K0  4225
#define KP  4352            // array stride / N padding (34 x 128)
#define MROWS 8192
#define LSEQ 1024
#define BK  64
#define NT  66              // mainloop K = 4224; k=4224 handled by rank-1 epilogue fixup

// ---------------- scratch ----------------
__device__ __half g_A[(size_t)MROWS * KP];  // [m][Xh]
__device__ __half g_R[(size_t)MROWS * KP];  // [m][Rh]
__device__ __half g_B[(size_t)KP    * KP];  // [(b,d)][Wh] (pads stay 0)
__device__ __half g_Q[(size_t)MROWS * KP];  // [m][Qh]

// smem: 3 stages x (A 128x64 + B 128x64 fp16), 128B rows, XOR swizzle
#define TILE_B    (128 * 128)            // 16384 B per tile
#define STAGE_B   (2 * TILE_B)           // 32768 B
#define SMEM_SZ   (3 * STAGE_B)          // 98304 B

// ---------------- PTX helpers ----------------
__device__ __forceinline__ uint32_t s2u(const void* p) {
    uint32_t a;
    asm("{ .reg .u64 t; cvta.to.shared.u64 t, %1; cvt.u32.u64 %0, t; }"
        : "=r"(a) : "l"(p));
    return a;
}
__device__ __forceinline__ void cp16(uint32_t s, const void* g) {
    asm volatile("cp.async.cg.shared.global [%0], [%1], 16;\n" :: "r"(s), "l"(g));
}
#define CP_COMMIT() asm volatile("cp.async.commit_group;\n" ::: "memory")
#define CP_WAIT1()  asm volatile("cp.async.wait_group 1;\n" ::: "memory")

#define LDM_X4(r0, r1, r2, r3, a)                                              \
    asm volatile("ldmatrix.sync.aligned.m8n8.x4.shared.b16 {%0,%1,%2,%3}, [%4];" \
        : "=r"(r0), "=r"(r1), "=r"(r2), "=r"(r3) : "r"(a))

#define MMA16816(c, a, b0, b1)                                                 \
    asm volatile("mma.sync.aligned.m16n8k16.row.col.f32.f16.f16.f32 "          \
        "{%0,%1,%2,%3}, {%4,%5,%6,%7}, {%8,%9}, {%0,%1,%2,%3};"                \
        : "+f"((c)[0]), "+f"((c)[1]), "+f"((c)[2]), "+f"((c)[3])               \
        : "r"((a)[0]), "r"((a)[1]), "r"((a)[2]), "r"((a)[3]),                  \
          "r"(b0), "r"(b1))

// ---------------- prep kernels ----------------
__global__ void prep_XR(const float* __restrict__ l1, const float* __restrict__ l2,
                        const float* __restrict__ h1, const float* __restrict__ h2) {
    int m = blockIdx.y;
    int k = blockIdx.x * blockDim.x + threadIdx.x;   // 0..KP-1
    float xv = 0.f, rv = 0.f;
    if (k < K0) {
        int a = k / D65, c = k - a * D65;
        float l1v = (a < 64) ? l1[m * 64 + a] : 1.0f;
        float l2v = (a < 64) ? l2[m * 64 + a] : 1.0f;
        xv = l1v * h1[m * D65 + c];
        rv = l2v * h2[m * D65 + c];
    }
    size_t base = (size_t)m * KP;
    g_A[base + k] = __float2half_rn(xv);
    g_R[base + k] = __float2half_rn(rv);
}

// g_B[(b*65+d)][a*65+c] = W[a][b][c][d] rounded to fp16
__global__ void prep_W(const float* __restrict__ W) {
    __shared__ float s[K0];
    int ab = blockIdx.x;
    int a = ab / D65, b = ab - a * D65;
    const float* Wab = W + (size_t)ab * K0;
    for (int i = threadIdx.x; i < K0; i += blockDim.x) s[i] = Wab[i];
    __syncthreads();
    for (int i = threadIdx.x; i < K0; i += blockDim.x) {
        int d = i / D65, c = i - d * D65;
        g_B[(size_t)(b * D65 + d) * KP + a * D65 + c] = __float2half_rn(s[c * D65 + d]);
    }
}

// ---------------- stage loader: 128x64 fp16 for A and B -------------------
// smem addr: row*128 + ((chunk ^ (row&7)) * 16), chunk = 16B column index
__device__ __forceinline__ void load_stage(uint32_t smA, uint32_t smB,
                                           const __half* Ab,
                                           const __half* Bb, int tid) {
#pragma unroll
    for (int t = 0; t < 4; t++) {
        int id = tid + t * 256;
        int r = id >> 3, c = id & 7;
        uint32_t off = r * 128 + ((c ^ (r & 7)) << 4);
        cp16(smA + off, Ab + (size_t)r * KP + c * 8);
        cp16(smB + off, Bb + (size_t)r * KP + c * 8);
    }
}

// ---------------- HMMA mainloop: acc[2][8][4] = A(128x4224) * B(128x4224)^T
__device__ __forceinline__ void hmma_loop(const __half* Abase,
                                          const __half* Bbase,
                                          uint32_t smb, int tid,
                                          float acc[2][8][4]) {
    int lane = tid & 31, wid = tid >> 5;
    int warp_m = wid & 3, warp_n = wid >> 2;

#pragma unroll
    for (int i = 0; i < 2; i++)
#pragma unroll
        for (int j = 0; j < 8; j++)
#pragma unroll
            for (int t = 0; t < 4; t++) acc[i][j][t] = 0.f;

    // ldmatrix per-lane rows and 8-element column halves
    int a_row  = 32 * warp_m + (lane & 7) + ((lane >> 3) & 1) * 8;
    int a_ch   = (lane >> 4) & 1;          // 8-elem half -> chunk offset
    int b_row  = 64 * warp_n + (lane & 7) + ((lane >> 4) & 1) * 8;
    int b_ch   = (lane >> 3) & 1;

    load_stage(smb, smb + TILE_B, Abase, Bbase, tid);
    CP_COMMIT();
    load_stage(smb + STAGE_B, smb + STAGE_B + TILE_B, Abase + BK, Bbase + BK, tid);
    CP_COMMIT();

    // rotating stage pointers: s0 = compute stage (kt%3), s2 = load stage ((kt+2)%3)
    uint32_t s0 = smb, s1 = smb + STAGE_B, s2 = smb + 2 * STAGE_B;

    for (int kt = 0; kt < NT; kt++) {
        CP_WAIT1();
        __syncthreads();
        uint32_t sA = s0;
        uint32_t sB = s0 + TILE_B;
        if (kt + 2 < NT) {
            load_stage(s2, s2 + TILE_B,
                       Abase + (size_t)(kt + 2) * BK,
                       Bbase + (size_t)(kt + 2) * BK, tid);
        }
        CP_COMMIT();
        // rotate for next iteration
        uint32_t tmp = s0; s0 = s1; s1 = s2; s2 = tmp;

#pragma unroll
        for (int ks = 0; ks < 4; ks++) {
            int kc = ks * 2;                 // base 16B-chunk of this k16
            uint32_t af[2][4];
#pragma unroll
            for (int i = 0; i < 2; i++) {
                int r = a_row + 16 * i;
                uint32_t addr = sA + r * 128 + (((kc + a_ch) ^ (r & 7)) << 4);
                LDM_X4(af[i][0], af[i][1], af[i][2], af[i][3], addr);
            }
            uint32_t bf[8][2];
#pragma unroll
            for (int j2 = 0; j2 < 4; j2++) {
                int r = b_row + 16 * j2;
                uint32_t addr = sB + r * 128 + (((kc + b_ch) ^ (r & 7)) << 4);
                LDM_X4(bf[2 * j2][0], bf[2 * j2][1],
                       bf[2 * j2 + 1][0], bf[2 * j2 + 1][1], addr);
            }
#pragma unroll
            for (int i = 0; i < 2; i++)
#pragma unroll
                for (int j = 0; j < 8; j++)
                    MMA16816(acc[i][j], af[i], bf[j][0], bf[j][1]);
        }
        // no trailing barrier: next iteration's top barrier protects reuse
    }
}

// rank-1 fixup for the dropped k=4224 term: acc += va[row] * vb[col]
// va/vb are fp16 vectors in global; rows/cols per the epilogue mapping.
__device__ __forceinline__ void rank1_fixup(float acc[2][8][4],
                                            const __half* va, size_t va_stride,
                                            const __half* vb, size_t vb_stride,
                                            int row0, int col0) {
    float ar[4], bc[16];
#pragma unroll
    for (int i = 0; i < 2; i++)
#pragma unroll
        for (int h = 0; h < 2; h++)
            ar[2 * i + h] = __half2float(va[(size_t)(row0 + 16 * i + 8 * h) * va_stride]);
#pragma unroll
    for (int j = 0; j < 8; j++) {
        bc[2 * j]     = __half2float(vb[(size_t)(col0 + 8 * j) * vb_stride]);
        bc[2 * j + 1] = __half2float(vb[(size_t)(col0 + 8 * j + 1) * vb_stride]);
    }
#pragma unroll
    for (int i = 0; i < 2; i++)
#pragma unroll
        for (int j = 0; j < 8; j++)
#pragma unroll
            for (int h = 0; h < 2; h++) {
                acc[i][j][2 * h]     += ar[2 * i + h] * bc[2 * j];
                acc[i][j][2 * h + 1] += ar[2 * i + h] * bc[2 * j + 1];
            }
}

// ---------------- GEMM1: Q = X @ W^T, epilogue fp16 -----------------------
__global__ void __launch_bounds__(256, 2) gemm1_kernel() {
    extern __shared__ char sm[];
    uint32_t smb = s2u(sm);
    int tid = threadIdx.x, lane = tid & 31, wid = tid >> 5;
    int warp_m = wid & 3, warp_n = wid >> 2;
    int brow = blockIdx.y * 128, bn = blockIdx.x * 128;

    float acc[2][8][4];
    hmma_loop(g_A + (size_t)brow * KP, g_B + (size_t)bn * KP, smb, tid, acc);

    int row0 = brow + 32 * warp_m + (lane >> 2);
    int col0 = bn + 64 * warp_n + (lane & 3) * 2;

    // k=4224 term: X[:,4224] (x) Wp[4224,:]  (g_B col-vector along its row dim)
    rank1_fixup(acc, g_A + 4224, KP, g_B + 4224, KP, row0, col0);

#pragma unroll
    for (int i = 0; i < 2; i++) {
#pragma unroll
        for (int j = 0; j < 8; j++) {
#pragma unroll
            for (int half = 0; half < 2; half++) {
                int r = row0 + 16 * i + 8 * half;
                int c = col0 + 8 * j;
                __half2 hh;
                hh.x = __float2half_rn(acc[i][j][2 * half]);
                hh.y = __float2half_rn(acc[i][j][2 * half + 1]);
                *reinterpret_cast<__half2*>(&g_Q[(size_t)r * KP + c]) = hh;
            }
        }
    }
}

// ---------------- GEMM2: out[n] = Q[n] @ R[n]^T, fp32 epilogue ------------
__global__ void __launch_bounds__(256, 2) gemm2_kernel(float* __restrict__ out) {
    extern __shared__ char sm[];
    uint32_t smb = s2u(sm);
    int tid = threadIdx.x, lane = tid & 31, wid = tid >> 5;
    int warp_m = wid & 3, warp_n = wid >> 2;
    int nb = blockIdx.z;
    int brow = blockIdx.y * 128, bn = blockIdx.x * 128;

    float acc[2][8][4];
    hmma_loop(g_Q + ((size_t)nb * LSEQ + brow) * KP,
              g_R + ((size_t)nb * LSEQ + bn) * KP, smb, tid, acc);

    int row0 = brow + 32 * warp_m + (lane >> 2);
    int col0 = bn + 64 * warp_n + (lane & 3) * 2;

    // k=4224 term: Q[:,4224] (x) R[:,4224] within this batch
    rank1_fixup(acc,
                g_Q + ((size_t)nb * LSEQ) * KP + 4224, KP,
                g_R + ((size_t)nb * LSEQ) * KP + 4224, KP,
                row0, col0);

    float* obase = out + (size_t)nb * LSEQ * LSEQ;
#pragma unroll
    for (int i = 0; i < 2; i++) {
#pragma unroll
        for (int j = 0; j < 8; j++) {
#pragma unroll
            for (int half = 0; half < 2; half++) {
                int r = row0 + 16 * i + 8 * half;
                int c = col0 + 8 * j;
                float2 v = make_float2(acc[i][j][2 * half], acc[i][j][2 * half + 1]);
                *reinterpret_cast<float2*>(&obase[(size_t)r * LSEQ + c]) = v;
            }
        }
    }
}

// ---------------- launcher ------------------------------------------------
extern "C" void kernel_launch(void* const* d_in, const int* in_sizes, int n_in,
                              void* d_out, int out_size) {
    const float* l1 = (const float*)d_in[0];
    const float* l2 = (const float*)d_in[1];
    const float* h1 = (const float*)d_in[3];
    const float* h2 = (const float*)d_in[4];
    const float* W  = (const float*)d_in[6];
    float* out = (float*)d_out;

    cudaFuncSetAttribute(gemm1_kernel, cudaFuncAttributeMaxDynamicSharedMemorySize, SMEM_SZ);
    cudaFuncSetAttribute(gemm2_kernel, cudaFuncAttributeMaxDynamicSharedMemorySize, SMEM_SZ);

    prep_XR<<<dim3(17, MROWS), 256>>>(l1, l2, h1, h2);
    prep_W<<<D65 * D65, 256>>>(W);
    gemm1_kernel<<<dim3(34, 64), 256, SMEM_SZ>>>();        // 34 N-tiles: Q cols 0..4351 (incl 4224)
    gemm2_kernel<<<dim3(8, 8, 8), 256, SMEM_SZ>>>(out);    // grid.x=8: full 1024 cols
}

// round 17
// speedup vs baseline: 1.4674x; 1.0001x over previous
#include <cuda_runtime.h>
#include <cuda_fp16.h>
#include <cstdint>

#define D65 65
#define K0  4225
#define KP  4352            // array stride / N padding (34 x 128)
#define MROWS 8192
#define LSEQ 1024
#define BK  64
#define NT  66              // mainloop K = 4224; k=4224 handled by rank-1 epilogue fixup

// ---------------- scratch ----------------
__device__ __half g_A[(size_t)MROWS * KP];  // [m][Xh]
__device__ __half g_R[(size_t)MROWS * KP];  // [m][Rh]
__device__ __half g_B[(size_t)KP    * KP];  // [(b,d)][Wh] (pads stay 0)
__device__ __half g_Q[(size_t)MROWS * KP];  // [m][Qh]

// smem: 3 stages x (A 128x64 + B 128x64 fp16), 128B rows, XOR swizzle
#define TILE_B    (128 * 128)            // 16384 B per tile
#define STAGE_B   (2 * TILE_B)           // 32768 B
#define SMEM_SZ   (3 * STAGE_B)          // 98304 B

// ---------------- PTX helpers ----------------
__device__ __forceinline__ uint32_t s2u(const void* p) {
    uint32_t a;
    asm("{ .reg .u64 t; cvta.to.shared.u64 t, %1; cvt.u32.u64 %0, t; }"
        : "=r"(a) : "l"(p));
    return a;
}
__device__ __forceinline__ void cp16(uint32_t s, const void* g) {
    asm volatile("cp.async.cg.shared.global [%0], [%1], 16;\n" :: "r"(s), "l"(g));
}
#define CP_COMMIT() asm volatile("cp.async.commit_group;\n" ::: "memory")
#define CP_WAIT1()  asm volatile("cp.async.wait_group 1;\n" ::: "memory")

#define LDM_X4(r0, r1, r2, r3, a)                                              \
    asm volatile("ldmatrix.sync.aligned.m8n8.x4.shared.b16 {%0,%1,%2,%3}, [%4];" \
        : "=r"(r0), "=r"(r1), "=r"(r2), "=r"(r3) : "r"(a))

#define MMA16816(c, a, b0, b1)                                                 \
    asm volatile("mma.sync.aligned.m16n8k16.row.col.f32.f16.f16.f32 "          \
        "{%0,%1,%2,%3}, {%4,%5,%6,%7}, {%8,%9}, {%0,%1,%2,%3};"                \
        : "+f"((c)[0]), "+f"((c)[1]), "+f"((c)[2]), "+f"((c)[3])               \
        : "r"((a)[0]), "r"((a)[1]), "r"((a)[2]), "r"((a)[3]),                  \
          "r"(b0), "r"(b1))

// anti-phase stagger: co-resident wave-slot partners differ by ~148 in linear
// bid; delay the odd slot by ~half a k-tile period so the two CTAs' sync
// windows cover each other's tensor-pipe bubbles. Output-invariant.
__device__ __forceinline__ void stagger_delay() {
    uint32_t linbid = blockIdx.x + gridDim.x * (blockIdx.y + gridDim.y * blockIdx.z);
    if ((linbid / 148) & 1) {
        uint64_t t0 = clock64();
        while (clock64() - t0 < 1300) { }
    }
}

// ---------------- prep kernels ----------------
__global__ void prep_XR(const float* __restrict__ l1, const float* __restrict__ l2,
                        const float* __restrict__ h1, const float* __restrict__ h2) {
    int m = blockIdx.y;
    int k = blockIdx.x * blockDim.x + threadIdx.x;   // 0..KP-1
    float xv = 0.f, rv = 0.f;
    if (k < K0) {
        int a = k / D65, c = k - a * D65;
        float l1v = (a < 64) ? l1[m * 64 + a] : 1.0f;
        float l2v = (a < 64) ? l2[m * 64 + a] : 1.0f;
        xv = l1v * h1[m * D65 + c];
        rv = l2v * h2[m * D65 + c];
    }
    size_t base = (size_t)m * KP;
    g_A[base + k] = __float2half_rn(xv);
    g_R[base + k] = __float2half_rn(rv);
}

// g_B[(b*65+d)][a*65+c] = W[a][b][c][d] rounded to fp16
__global__ void prep_W(const float* __restrict__ W) {
    __shared__ float s[K0];
    int ab = blockIdx.x;
    int a = ab / D65, b = ab - a * D65;
    const float* Wab = W + (size_t)ab * K0;
    for (int i = threadIdx.x; i < K0; i += blockDim.x) s[i] = Wab[i];
    __syncthreads();
    for (int i = threadIdx.x; i < K0; i += blockDim.x) {
        int d = i / D65, c = i - d * D65;
        g_B[(size_t)(b * D65 + d) * KP + a * D65 + c] = __float2half_rn(s[c * D65 + d]);
    }
}

// ---------------- stage loader: 128x64 fp16 for A and B -------------------
// smem addr: row*128 + ((chunk ^ (row&7)) * 16), chunk = 16B column index
__device__ __forceinline__ void load_stage(uint32_t smA, uint32_t smB,
                                           const __half* Ab,
                                           const __half* Bb, int tid) {
#pragma unroll
    for (int t = 0; t < 4; t++) {
        int id = tid + t * 256;
        int r = id >> 3, c = id & 7;
        uint32_t off = r * 128 + ((c ^ (r & 7)) << 4);
        cp16(smA + off, Ab + (size_t)r * KP + c * 8);
        cp16(smB + off, Bb + (size_t)r * KP + c * 8);
    }
}

// ---------------- HMMA mainloop: acc[2][8][4] = A(128x4224) * B(128x4224)^T
__device__ __forceinline__ void hmma_loop(const __half* Abase,
                                          const __half* Bbase,
                                          uint32_t smb, int tid,
                                          float acc[2][8][4]) {
    int lane = tid & 31, wid = tid >> 5;
    int warp_m = wid & 3, warp_n = wid >> 2;

#pragma unroll
    for (int i = 0; i < 2; i++)
#pragma unroll
        for (int j = 0; j < 8; j++)
#pragma unroll
            for (int t = 0; t < 4; t++) acc[i][j][t] = 0.f;

    // ldmatrix per-lane rows and 8-element column halves
    int a_row  = 32 * warp_m + (lane & 7) + ((lane >> 3) & 1) * 8;
    int a_ch   = (lane >> 4) & 1;          // 8-elem half -> chunk offset
    int b_row  = 64 * warp_n + (lane & 7) + ((lane >> 4) & 1) * 8;
    int b_ch   = (lane >> 3) & 1;

    load_stage(smb, smb + TILE_B, Abase, Bbase, tid);
    CP_COMMIT();
    load_stage(smb + STAGE_B, smb + STAGE_B + TILE_B, Abase + BK, Bbase + BK, tid);
    CP_COMMIT();

    // rotating stage pointers: s0 = compute stage (kt%3), s2 = load stage ((kt+2)%3)
    uint32_t s0 = smb, s1 = smb + STAGE_B, s2 = smb + 2 * STAGE_B;

    for (int kt = 0; kt < NT; kt++) {
        CP_WAIT1();
        __syncthreads();
        uint32_t sA = s0;
        uint32_t sB = s0 + TILE_B;
        if (kt + 2 < NT) {
            load_stage(s2, s2 + TILE_B,
                       Abase + (size_t)(kt + 2) * BK,
                       Bbase + (size_t)(kt + 2) * BK, tid);
        }
        CP_COMMIT();
        // rotate for next iteration
        uint32_t tmp = s0; s0 = s1; s1 = s2; s2 = tmp;

#pragma unroll
        for (int ks = 0; ks < 4; ks++) {
            int kc = ks * 2;                 // base 16B-chunk of this k16
            uint32_t af[2][4];
#pragma unroll
            for (int i = 0; i < 2; i++) {
                int r = a_row + 16 * i;
                uint32_t addr = sA + r * 128 + (((kc + a_ch) ^ (r & 7)) << 4);
                LDM_X4(af[i][0], af[i][1], af[i][2], af[i][3], addr);
            }
            uint32_t bf[8][2];
#pragma unroll
            for (int j2 = 0; j2 < 4; j2++) {
                int r = b_row + 16 * j2;
                uint32_t addr = sB + r * 128 + (((kc + b_ch) ^ (r & 7)) << 4);
                LDM_X4(bf[2 * j2][0], bf[2 * j2][1],
                       bf[2 * j2 + 1][0], bf[2 * j2 + 1][1], addr);
            }
#pragma unroll
            for (int i = 0; i < 2; i++)
#pragma unroll
                for (int j = 0; j < 8; j++)
                    MMA16816(acc[i][j], af[i], bf[j][0], bf[j][1]);
        }
        // no trailing barrier: next iteration's top barrier protects reuse
    }
}

// rank-1 fixup for the dropped k=4224 term: acc += va[row] * vb[col]
__device__ __forceinline__ void rank1_fixup(float acc[2][8][4],
                                            const __half* va, size_t va_stride,
                                            const __half* vb, size_t vb_stride,
                                            int row0, int col0) {
    float ar[4], bc[16];
#pragma unroll
    for (int i = 0; i < 2; i++)
#pragma unroll
        for (int h = 0; h < 2; h++)
            ar[2 * i + h] = __half2float(va[(size_t)(row0 + 16 * i + 8 * h) * va_stride]);
#pragma unroll
    for (int j = 0; j < 8; j++) {
        bc[2 * j]     = __half2float(vb[(size_t)(col0 + 8 * j) * vb_stride]);
        bc[2 * j + 1] = __half2float(vb[(size_t)(col0 + 8 * j + 1) * vb_stride]);
    }
#pragma unroll
    for (int i = 0; i < 2; i++)
#pragma unroll
        for (int j = 0; j < 8; j++)
#pragma unroll
            for (int h = 0; h < 2; h++) {
                acc[i][j][2 * h]     += ar[2 * i + h] * bc[2 * j];
                acc[i][j][2 * h + 1] += ar[2 * i + h] * bc[2 * j + 1];
            }
}

// ---------------- GEMM1: Q = X @ W^T, epilogue fp16 -----------------------
__global__ void __launch_bounds__(256, 2) gemm1_kernel() {
    extern __shared__ char sm[];
    uint32_t smb = s2u(sm);
    int tid = threadIdx.x, lane = tid & 31, wid = tid >> 5;
    int warp_m = wid & 3, warp_n = wid >> 2;
    int brow = blockIdx.y * 128, bn = blockIdx.x * 128;

    stagger_delay();

    float acc[2][8][4];
    hmma_loop(g_A + (size_t)brow * KP, g_B + (size_t)bn * KP, smb, tid, acc);

    int row0 = brow + 32 * warp_m + (lane >> 2);
    int col0 = bn + 64 * warp_n + (lane & 3) * 2;

    // k=4224 term: X[:,4224] (x) Wp[4224,:]
    rank1_fixup(acc, g_A + 4224, KP, g_B + 4224, KP, row0, col0);

#pragma unroll
    for (int i = 0; i < 2; i++) {
#pragma unroll
        for (int j = 0; j < 8; j++) {
#pragma unroll
            for (int half = 0; half < 2; half++) {
                int r = row0 + 16 * i + 8 * half;
                int c = col0 + 8 * j;
                __half2 hh;
                hh.x = __float2half_rn(acc[i][j][2 * half]);
                hh.y = __float2half_rn(acc[i][j][2 * half + 1]);
                *reinterpret_cast<__half2*>(&g_Q[(size_t)r * KP + c]) = hh;
            }
        }
    }
}

// ---------------- GEMM2: out[n] = Q[n] @ R[n]^T, fp32 epilogue ------------
__global__ void __launch_bounds__(256, 2) gemm2_kernel(float* __restrict__ out) {
    extern __shared__ char sm[];
    uint32_t smb = s2u(sm);
    int tid = threadIdx.x, lane = tid & 31, wid = tid >> 5;
    int warp_m = wid & 3, warp_n = wid >> 2;
    int nb = blockIdx.z;
    int brow = blockIdx.y * 128, bn = blockIdx.x * 128;

    stagger_delay();

    float acc[2][8][4];
    hmma_loop(g_Q + ((size_t)nb * LSEQ + brow) * KP,
              g_R + ((size_t)nb * LSEQ + bn) * KP, smb, tid, acc);

    int row0 = brow + 32 * warp_m + (lane >> 2);
    int col0 = bn + 64 * warp_n + (lane & 3) * 2;

    // k=4224 term: Q[:,4224] (x) R[:,4224] within this batch
    rank1_fixup(acc,
                g_Q + ((size_t)nb * LSEQ) * KP + 4224, KP,
                g_R + ((size_t)nb * LSEQ) * KP + 4224, KP,
                row0, col0);

    float* obase = out + (size_t)nb * LSEQ * LSEQ;
#pragma unroll
    for (int i = 0; i < 2; i++) {
#pragma unroll
        for (int j = 0; j < 8; j++) {
#pragma unroll
            for (int half = 0; half < 2; half++) {
                int r = row0 + 16 * i + 8 * half;
                int c = col0 + 8 * j;
                float2 v = make_float2(acc[i][j][2 * half], acc[i][j][2 * half + 1]);
                *reinterpret_cast<float2*>(&obase[(size_t)r * LSEQ + c]) = v;
            }
        }
    }
}

// ---------------- launcher ------------------------------------------------
extern "C" void kernel_launch(void* const* d_in, const int* in_sizes, int n_in,
                              void* d_out, int out_size) {
    const float* l1 = (const float*)d_in[0];
    const float* l2 = (const float*)d_in[1];
    const float* h1 = (const float*)d_in[3];
    const float* h2 = (const float*)d_in[4];
    const float* W  = (const float*)d_in[6];
    float* out = (float*)d_out;

    cudaFuncSetAttribute(gemm1_kernel, cudaFuncAttributeMaxDynamicSharedMemorySize, SMEM_SZ);
    cudaFuncSetAttribute(gemm2_kernel, cudaFuncAttributeMaxDynamicSharedMemorySize, SMEM_SZ);

    prep_XR<<<dim3(17, MROWS), 256>>>(l1, l2, h1, h2);
    prep_W<<<D65 * D65, 256>>>(W);
    gemm1_kernel<<<dim3(34, 64), 256, SMEM_SZ>>>();
    gemm2_kernel<<<dim3(8, 8, 8), 256, SMEM_SZ>>>(out);
}